// round 16
// baseline (speedup 1.0000x reference)
#include <cuda_runtime.h>
#include <cuda_bf16.h>

// Problem constants
#define NF 8
#define V 12
#define D 64
#define BATCH 131072
#define NPAIR 28                         // C(8,2)
#define GRAM_DOTS 4032                   // 28 * 144 floats = 16128 B (fits L1)

// Device globals (no allocation allowed)
__device__ float    g_gram[GRAM_DOTS];    // [pair][i][j] = dot(emb[f][i], emb[g][j])
__device__ float2   g_pf[NF * V];         // (.x=dot(e,a0)+first, .y=dot(e,a1)+first)
__device__ float    g_partial[512];       // per-block weighted-loss partials
__device__ unsigned g_done;               // last-block counter (self-wrapping)

__device__ __forceinline__ float dot4(float4 a, float4 b) {
    return a.x * b.x + a.y * b.y + a.z * b.z + a.w * b.w;
}

// ---------------------------------------------------------------------------
// Kernel 1: precompute gram + PF tables.
// Each 64-length dot split across 4 threads (16 floats each), shfl-reduced.
// 4032 gram dots + 96 PF units = 4128 units * 4 = 16512 threads (warp-aligned).
// ---------------------------------------------------------------------------
#define PRE_THREADS 256
#define TOTAL_DOTS (GRAM_DOTS + NF * V)                                // 4128
#define PRE_BLOCKS ((TOTAL_DOTS * 4 + PRE_THREADS - 1) / PRE_THREADS)  // 65

__global__ void __launch_bounds__(PRE_THREADS)
precompute_kernel(const float* __restrict__ emb,
                  const float* __restrict__ emb_first,
                  const float* __restrict__ a_emb)
{
    int gid  = blockIdx.x * PRE_THREADS + threadIdx.x;
    int dot  = gid >> 2;
    int part = gid & 3;
    if (dot >= TOTAL_DOTS) return;       // whole warps only (16512 % 32 == 0)

    if (dot < GRAM_DOTS) {
        int p = dot / (V * V);
        int r = dot - p * (V * V);
        int i = r / V, j = r - (r / V) * V;
        // decode pair p -> (f, g), f < g, order (0,1),(0,2),...,(6,7)
        int f = 0, g = 1, c = p;
        #pragma unroll
        for (int ff = 0; ff < NF - 1; ++ff) {
            int cnt = NF - 1 - ff;
            if (c < cnt) { f = ff; g = ff + 1 + c; break; }
            c -= cnt;
        }
        const float4* ra = (const float4*)(emb + (size_t)(f * V + i) * D) + part * 4;
        const float4* rb = (const float4*)(emb + (size_t)(g * V + j) * D) + part * 4;
        float4 a0 = __ldg(&ra[0]), b0 = __ldg(&rb[0]);
        float4 a1 = __ldg(&ra[1]), b1 = __ldg(&rb[1]);
        float4 a2 = __ldg(&ra[2]), b2 = __ldg(&rb[2]);
        float4 a3 = __ldg(&ra[3]), b3 = __ldg(&rb[3]);
        float s = (dot4(a0, b0) + dot4(a2, b2)) + (dot4(a1, b1) + dot4(a3, b3));
        s += __shfl_xor_sync(0xffffffffu, s, 1);
        s += __shfl_xor_sync(0xffffffffu, s, 2);
        if (part == 0) g_gram[dot] = s;
    } else {
        int t = dot - GRAM_DOTS;         // 0..95 = f*V + i
        const float4* rr = (const float4*)(emb + (size_t)t * D) + part * 4;
        const float4* a0 = (const float4*)(a_emb) + part * 4;
        const float4* a1 = (const float4*)(a_emb + D) + part * 4;
        float s0 = 0.f, s1 = 0.f;
        #pragma unroll
        for (int q = 0; q < 4; ++q) {
            float4 e = __ldg(&rr[q]);
            float4 x = __ldg(&a0[q]);
            float4 y = __ldg(&a1[q]);
            s0 += dot4(e, x);
            s1 += dot4(e, y);
        }
        s0 += __shfl_xor_sync(0xffffffffu, s0, 1);
        s0 += __shfl_xor_sync(0xffffffffu, s0, 2);
        s1 += __shfl_xor_sync(0xffffffffu, s1, 1);
        s1 += __shfl_xor_sync(0xffffffffu, s1, 2);
        if (part == 0) {
            float fo = __ldg(&emb_first[t]);
            g_pf[t] = make_float2(s0 + fo, s1 + fo);        // first-order folded
        }
    }
}

// ---------------------------------------------------------------------------
// Kernel 2: main kernel — NO smem table, NO staging, NO table sync.
// Gram (16 KB) and PF (768 B) are read via __ldg and live in L1 after first
// touch. Occupancy is regs-limited only. Fused last-block loss finalize.
// ---------------------------------------------------------------------------
#define THREADS 256
#define NBLK 512                          // 512 * 256 = 131072 = BATCH

__global__ void __launch_bounds__(THREADS)
fm_main_kernel(const int* __restrict__ feats,
               const float* __restrict__ label,
               const float* __restrict__ pos_weights,
               const float* __restrict__ action_first,
               float* __restrict__ out)
{
    __shared__ float s_wsum[THREADS / 32];
    __shared__ int   s_is_last;

    const int tid = threadIdx.x;
    const int b   = blockIdx.x * THREADS + tid;

    // Front-batched global loads (coalesced; feats is [field][batch])
    int idx[NF];
    #pragma unroll
    for (int f = 0; f < NF; ++f)
        idx[f] = __ldg(&feats[f * BATCH + b]);
    float2 lab = __ldg(((const float2*)label) + b);
    float2 pw  = __ldg(((const float2*)pos_weights) + b);
    const float af0 = __ldg(&action_first[0]);
    const float af1 = __ldg(&action_first[1]);

    // First order + action dots: 8 L1-resident float2 gathers
    float d0 = 0.f, d1 = 0.f;
    #pragma unroll
    for (int f = 0; f < NF; ++f) {
        float2 pf = __ldg(&g_pf[f * V + idx[f]]);
        d0 += pf.x; d1 += pf.y;
    }

    // Pairwise: 28 L1-resident scalar gathers into the 16 KB gram table
    float pair = 0.f;
    int p = 0;
    #pragma unroll
    for (int f = 0; f < NF; ++f) {
        int base_f = idx[f] * V;
        #pragma unroll
        for (int g = f + 1; g < NF; ++g) {
            pair += __ldg(&g_gram[p * (V * V) + base_f + idx[g]]);
            ++p;
        }
    }

    float inf0 = d0 + af0;
    float inf1 = d1 + af1;
    float e0 = inf0 - lab.x;
    float e1 = inf1 - lab.y;
    float lsum = pw.x * e0 * e0 + pw.y * e1 * e1;

    // Outputs: inferences [B,2] at [0,2B), loss at 2B, pair [B,1] after it
    ((float2*)out)[b] = make_float2(inf0, inf1);
    out[2 * BATCH + 1 + b] = pair;

    // Block reduction of weighted loss (full-warp shuffles only)
    #pragma unroll
    for (int o = 16; o > 0; o >>= 1) lsum += __shfl_xor_sync(0xffffffffu, lsum, o);
    if ((tid & 31) == 0) s_wsum[tid >> 5] = lsum;
    __syncthreads();
    if (tid < 32) {
        float v = (tid < THREADS / 32) ? s_wsum[tid] : 0.f;
        #pragma unroll
        for (int o = 16; o > 0; o >>= 1) v += __shfl_xor_sync(0xffffffffu, v, o);
        if (tid == 0) {
            g_partial[blockIdx.x] = v;
            __threadfence();
            unsigned old = atomicInc(&g_done, NBLK - 1);   // wraps -> self-reset
            s_is_last = (old == NBLK - 1);
        }
    }
    __syncthreads();

    // Last-finishing block: reduce NBLK=512 partials (2 per thread), write mean.
    if (s_is_last) {
        __threadfence();
        float v = g_partial[tid] + g_partial[tid + THREADS];
        #pragma unroll
        for (int o = 16; o > 0; o >>= 1) v += __shfl_xor_sync(0xffffffffu, v, o);
        if ((tid & 31) == 0) s_wsum[tid >> 5] = v;
        __syncthreads();
        if (tid < 32) {
            float w = (tid < THREADS / 32) ? s_wsum[tid] : 0.f;
            #pragma unroll
            for (int o = 16; o > 0; o >>= 1) w += __shfl_xor_sync(0xffffffffu, w, o);
            if (tid == 0) out[2 * BATCH] = w * (1.0f / (float)BATCH);
        }
    }
}

// ---------------------------------------------------------------------------
// Launch. Inputs (metadata order):
//   0 emb_tables (8,12,64) f32   1 emb_first (8,12,1) f32
//   2 action_emb (2,64) f32      3 action_first (2,1) f32
//   4 label (B,2) f32            5 pos_weights (B,2) f32
//   6 feats (8,B) i32
// Output: [inferences (B,2) | loss (1) | pair (B,1)] f32
// ---------------------------------------------------------------------------
extern "C" void kernel_launch(void* const* d_in, const int* in_sizes, int n_in,
                              void* d_out, int out_size)
{
    const float* emb_tables   = (const float*)d_in[0];
    const float* emb_first    = (const float*)d_in[1];
    const float* action_emb   = (const float*)d_in[2];
    const float* action_first = (const float*)d_in[3];
    const float* label        = (const float*)d_in[4];
    const float* pos_weights  = (const float*)d_in[5];
    const int*   feats        = (const int*)d_in[6];
    float* out = (float*)d_out;

    precompute_kernel<<<PRE_BLOCKS, PRE_THREADS>>>(emb_tables, emb_first, action_emb);
    fm_main_kernel<<<NBLK, THREADS>>>(feats, label, pos_weights, action_first, out);
}

// round 17
// speedup vs baseline: 1.0390x; 1.0390x over previous
#include <cuda_runtime.h>
#include <cuda_bf16.h>

// Problem constants
#define NF 8
#define V 12
#define D 64
#define BATCH 131072
#define NPAIR 28                         // C(8,2)
#define GRAM_DOTS 4032                   // 28 * 144
#define GRAM2_ELEMS (GRAM_DOTS * 2)      // interleaved-duplicated: 8064 floats

// Device globals (no allocation allowed)
__device__ float    g_gram2[GRAM2_ELEMS]; // [2e]=[2e+1]=dot(emb[f][i],emb[g][j])
__device__ float2   g_pf[NF * V];         // (.x=dot(e,a0)+first, .y=dot(e,a1)+first)
__device__ float    g_partial[256];       // per-block weighted-loss partials
__device__ unsigned g_done;               // last-block counter (self-wrapping)

__device__ __forceinline__ float dot4(float4 a, float4 b) {
    return a.x * b.x + a.y * b.y + a.z * b.z + a.w * b.w;
}

// ---------------------------------------------------------------------------
// Kernel 1: precompute gram (duplicated layout) + PF tables.
// Each 64-length dot split across 4 threads (16 floats each), shfl-reduced.
// 129 blocks x 128 threads = 16512 threads (warp-aligned; more SMs share the
// cold-L2 first-touch of the 24 KB embedding table).
// ---------------------------------------------------------------------------
#define PRE_THREADS 128
#define TOTAL_DOTS (GRAM_DOTS + NF * V)                                // 4128
#define PRE_BLOCKS ((TOTAL_DOTS * 4 + PRE_THREADS - 1) / PRE_THREADS)  // 129

__global__ void __launch_bounds__(PRE_THREADS)
precompute_kernel(const float* __restrict__ emb,
                  const float* __restrict__ emb_first,
                  const float* __restrict__ a_emb)
{
    int gid  = blockIdx.x * PRE_THREADS + threadIdx.x;
    int dot  = gid >> 2;
    int part = gid & 3;
    if (dot >= TOTAL_DOTS) return;       // whole warps only (16512 % 32 == 0)

    if (dot < GRAM_DOTS) {
        int p = dot / (V * V);
        int r = dot - p * (V * V);
        int i = r / V, j = r - (r / V) * V;
        // decode pair p -> (f, g), f < g, order (0,1),(0,2),...,(6,7)
        int f = 0, g = 1, c = p;
        #pragma unroll
        for (int ff = 0; ff < NF - 1; ++ff) {
            int cnt = NF - 1 - ff;
            if (c < cnt) { f = ff; g = ff + 1 + c; break; }
            c -= cnt;
        }
        const float4* ra = (const float4*)(emb + (size_t)(f * V + i) * D) + part * 4;
        const float4* rb = (const float4*)(emb + (size_t)(g * V + j) * D) + part * 4;
        float4 a0 = __ldg(&ra[0]), b0 = __ldg(&rb[0]);
        float4 a1 = __ldg(&ra[1]), b1 = __ldg(&rb[1]);
        float4 a2 = __ldg(&ra[2]), b2 = __ldg(&rb[2]);
        float4 a3 = __ldg(&ra[3]), b3 = __ldg(&rb[3]);
        float s = (dot4(a0, b0) + dot4(a2, b2)) + (dot4(a1, b1) + dot4(a3, b3));
        s += __shfl_xor_sync(0xffffffffu, s, 1);
        s += __shfl_xor_sync(0xffffffffu, s, 2);
        if (part == 0)
            ((float2*)g_gram2)[dot] = make_float2(s, s);   // duplicated layout
    } else {
        int t = dot - GRAM_DOTS;         // 0..95 = f*V + i
        const float4* rr = (const float4*)(emb + (size_t)t * D) + part * 4;
        const float4* a0 = (const float4*)(a_emb) + part * 4;
        const float4* a1 = (const float4*)(a_emb + D) + part * 4;
        float s0 = 0.f, s1 = 0.f;
        #pragma unroll
        for (int q = 0; q < 4; ++q) {
            float4 e = __ldg(&rr[q]);
            float4 x = __ldg(&a0[q]);
            float4 y = __ldg(&a1[q]);
            s0 += dot4(e, x);
            s1 += dot4(e, y);
        }
        s0 += __shfl_xor_sync(0xffffffffu, s0, 1);
        s0 += __shfl_xor_sync(0xffffffffu, s0, 2);
        s1 += __shfl_xor_sync(0xffffffffu, s1, 1);
        s1 += __shfl_xor_sync(0xffffffffu, s1, 2);
        if (part == 0) {
            float fo = __ldg(&emb_first[t]);
            g_pf[t] = make_float2(s0 + fo, s1 + fo);        // first-order folded
        }
    }
}

// ---------------------------------------------------------------------------
// Kernel 2: main kernel — R13's measured-best shape (256 blocks x 512, EPT=1,
// bank-split duplicated gram in smem, fused last-block loss finalize), with
// streaming cache hints on the per-element loads/stores so the 6 MB stream
// never evicts the hot tables.
// ---------------------------------------------------------------------------
#define THREADS 512
#define NBLK 256                          // 256 * 512 = 131072 = BATCH

__global__ void __launch_bounds__(THREADS)
fm_main_kernel(const int* __restrict__ feats,
               const float* __restrict__ label,
               const float* __restrict__ pos_weights,
               const float* __restrict__ action_first,
               float* __restrict__ out)
{
    __shared__ __align__(16) float s_gram2[GRAM2_ELEMS];   // 31.5 KB
    __shared__ float2 s_pf[NF * V];
    __shared__ float  s_wsum[THREADS / 32];
    __shared__ int    s_is_last;

    const int tid = threadIdx.x;
    const int b   = blockIdx.x * THREADS + tid;

    // Front-batched streaming loads (evict-first: protect table lines)
    int idx[NF];
    #pragma unroll
    for (int f = 0; f < NF; ++f)
        idx[f] = __ldcs(&feats[f * BATCH + b]);
    float2 lab = __ldcs(((const float2*)label) + b);
    float2 pw  = __ldcs(((const float2*)pos_weights) + b);
    const float af0 = __ldg(&action_first[0]);
    const float af1 = __ldg(&action_first[1]);

    // Stage duplicated gram (2016 float4) + PF into smem
    {
        const float4* src = (const float4*)g_gram2;
        float4* dst = (float4*)s_gram2;
        dst[tid]               = src[tid];
        dst[THREADS + tid]     = src[THREADS + tid];
        dst[2 * THREADS + tid] = src[2 * THREADS + tid];
        int k = 3 * THREADS + tid;
        if (k < GRAM2_ELEMS / 4) dst[k] = src[k];
        if (tid < NF * V) s_pf[tid] = g_pf[tid];
    }
    __syncthreads();

    // First order + action dots (8 LDS.64)
    float d0 = 0.f, d1 = 0.f;
    #pragma unroll
    for (int f = 0; f < NF; ++f) {
        float2 pf = s_pf[f * V + idx[f]];
        d0 += pf.x; d1 += pf.y;
    }

    // Pairwise: 28 gathers into the bank-split duplicated table.
    // Lanes 0-15 read even words, lanes 16-31 odd words.
    const int hi = (tid >> 4) & 1;
    float pair = 0.f;
    int p = 0;
    #pragma unroll
    for (int f = 0; f < NF; ++f) {
        int base_f = idx[f] * V;
        #pragma unroll
        for (int g = f + 1; g < NF; ++g) {
            pair += s_gram2[((p * (V * V) + base_f + idx[g]) << 1) | hi];
            ++p;
        }
    }

    float inf0 = d0 + af0;
    float inf1 = d1 + af1;
    float e0 = inf0 - lab.x;
    float e1 = inf1 - lab.y;
    float lsum = pw.x * e0 * e0 + pw.y * e1 * e1;

    // Streaming stores: inferences [B,2] at [0,2B), loss at 2B, pair after it
    __stcs(((float2*)out) + b, make_float2(inf0, inf1));
    __stcs(&out[2 * BATCH + 1 + b], pair);

    // Block reduction of weighted loss (full-warp shuffles only)
    #pragma unroll
    for (int o = 16; o > 0; o >>= 1) lsum += __shfl_xor_sync(0xffffffffu, lsum, o);
    if ((tid & 31) == 0) s_wsum[tid >> 5] = lsum;
    __syncthreads();
    if (tid < 32) {
        float v = (tid < THREADS / 32) ? s_wsum[tid] : 0.f;
        #pragma unroll
        for (int o = 16; o > 0; o >>= 1) v += __shfl_xor_sync(0xffffffffu, v, o);
        if (tid == 0) {
            g_partial[blockIdx.x] = v;
            __threadfence();
            unsigned old = atomicInc(&g_done, NBLK - 1);   // wraps -> self-reset
            s_is_last = (old == NBLK - 1);
        }
    }
    __syncthreads();

    // Last-finishing block: reduce NBLK partials, write mean loss.
    if (s_is_last) {
        __threadfence();
        float v = (tid < NBLK) ? g_partial[tid] : 0.f;
        #pragma unroll
        for (int o = 16; o > 0; o >>= 1) v += __shfl_xor_sync(0xffffffffu, v, o);
        if ((tid & 31) == 0) s_wsum[tid >> 5] = v;
        __syncthreads();
        if (tid < 32) {
            float w = (tid < THREADS / 32) ? s_wsum[tid] : 0.f;
            #pragma unroll
            for (int o = 16; o > 0; o >>= 1) w += __shfl_xor_sync(0xffffffffu, w, o);
            if (tid == 0) out[2 * BATCH] = w * (1.0f / (float)BATCH);
        }
    }
}

// ---------------------------------------------------------------------------
// Launch. Inputs (metadata order):
//   0 emb_tables (8,12,64) f32   1 emb_first (8,12,1) f32
//   2 action_emb (2,64) f32      3 action_first (2,1) f32
//   4 label (B,2) f32            5 pos_weights (B,2) f32
//   6 feats (8,B) i32
// Output: [inferences (B,2) | loss (1) | pair (B,1)] f32
// ---------------------------------------------------------------------------
extern "C" void kernel_launch(void* const* d_in, const int* in_sizes, int n_in,
                              void* d_out, int out_size)
{
    const float* emb_tables   = (const float*)d_in[0];
    const float* emb_first    = (const float*)d_in[1];
    const float* action_emb   = (const float*)d_in[2];
    const float* action_first = (const float*)d_in[3];
    const float* label        = (const float*)d_in[4];
    const float* pos_weights  = (const float*)d_in[5];
    const int*   feats        = (const int*)d_in[6];
    float* out = (float*)d_out;

    precompute_kernel<<<PRE_BLOCKS, PRE_THREADS>>>(emb_tables, emb_first, action_emb);
    fm_main_kernel<<<NBLK, THREADS>>>(feats, label, pos_weights, action_first, out);
}